// round 3
// baseline (speedup 1.0000x reference)
#include <cuda_runtime.h>
#include <cstdint>

#define NODE_CAP 102400   // >= num_nodes (100000)

// Scratch: device globals (allocation-free per harness rules)
__device__ int   g_emax_ord[NODE_CAP];   // float max as order-preserving int
__device__ float g_sumexp[NODE_CAP];

// Order-preserving float<->int bijection (involution).
__device__ __forceinline__ int f2o(float f) {
    int i = __float_as_int(f);
    return i >= 0 ? i : i ^ 0x7FFFFFFF;
}
__device__ __forceinline__ float o2f(int i) {
    return __int_as_float(i >= 0 ? i : i ^ 0x7FFFFFFF);
}

// ---------------- init ----------------
__global__ void k_init() {
    int i = blockIdx.x * blockDim.x + threadIdx.x;
    if (i < NODE_CAP) {
        g_emax_ord[i] = f2o(-1e9f);
        g_sumexp[i]   = 0.0f;
    }
}

// ---------------- pass 1: atomic max ----------------
__global__ void k_max(const float* __restrict__ e,
                      const int* __restrict__ tgt, int n) {
    int v = blockIdx.x * blockDim.x + threadIdx.x;
    int base = v * 4;
    if (base + 3 < n) {
        float4 ev = reinterpret_cast<const float4*>(e)[v];
        int4   t  = reinterpret_cast<const int4*>(tgt)[v];
        atomicMax(&g_emax_ord[t.x], f2o(ev.x));
        atomicMax(&g_emax_ord[t.y], f2o(ev.y));
        atomicMax(&g_emax_ord[t.z], f2o(ev.z));
        atomicMax(&g_emax_ord[t.w], f2o(ev.w));
    } else {
        for (int i = base; i < n; i++)
            atomicMax(&g_emax_ord[tgt[i]], f2o(e[i]));
    }
}

// ---------------- pass 2: atomic sum of exp(e - max) ----------------
__global__ void k_sum(const float* __restrict__ e,
                      const int* __restrict__ tgt, int n) {
    int v = blockIdx.x * blockDim.x + threadIdx.x;
    int base = v * 4;
    if (base + 3 < n) {
        float4 ev = reinterpret_cast<const float4*>(e)[v];
        int4   t  = reinterpret_cast<const int4*>(tgt)[v];
        float m0 = o2f(g_emax_ord[t.x]);
        float m1 = o2f(g_emax_ord[t.y]);
        float m2 = o2f(g_emax_ord[t.z]);
        float m3 = o2f(g_emax_ord[t.w]);
        atomicAdd(&g_sumexp[t.x], __expf(ev.x - m0));
        atomicAdd(&g_sumexp[t.y], __expf(ev.y - m1));
        atomicAdd(&g_sumexp[t.z], __expf(ev.z - m2));
        atomicAdd(&g_sumexp[t.w], __expf(ev.w - m3));
    } else {
        for (int i = base; i < n; i++) {
            int t = tgt[i];
            atomicAdd(&g_sumexp[t], __expf(e[i] - o2f(g_emax_ord[t])));
        }
    }
}

// ---------------- pass 3: alpha = exp(e - max) / (sum + eps) ----------------
__global__ void k_norm(const float* __restrict__ e,
                       const int* __restrict__ tgt,
                       float* __restrict__ out, int n) {
    int v = blockIdx.x * blockDim.x + threadIdx.x;
    int base = v * 4;
    if (base + 3 < n) {
        float4 ev = reinterpret_cast<const float4*>(e)[v];
        int4   t  = reinterpret_cast<const int4*>(tgt)[v];
        float m0 = o2f(g_emax_ord[t.x]);
        float m1 = o2f(g_emax_ord[t.y]);
        float m2 = o2f(g_emax_ord[t.z]);
        float m3 = o2f(g_emax_ord[t.w]);
        float4 r;
        r.x = __expf(ev.x - m0) / (g_sumexp[t.x] + 1e-16f);
        r.y = __expf(ev.y - m1) / (g_sumexp[t.y] + 1e-16f);
        r.z = __expf(ev.z - m2) / (g_sumexp[t.z] + 1e-16f);
        r.w = __expf(ev.w - m3) / (g_sumexp[t.w] + 1e-16f);
        reinterpret_cast<float4*>(out)[v] = r;
    } else {
        for (int i = base; i < n; i++) {
            int t = tgt[i];
            out[i] = __expf(e[i] - o2f(g_emax_ord[t])) / (g_sumexp[t] + 1e-16f);
        }
    }
}

extern "C" void kernel_launch(void* const* d_in, const int* in_sizes, int n_in,
                              void* d_out, int out_size) {
    const float* e   = (const float*)d_in[0];
    const int*   ei  = (const int*)d_in[1];   // int32 [2, n] (JAX x64-disabled)
    float*       out = (float*)d_out;
    int n = in_sizes[0];
    const int* tgt = ei + n;  // row 1 = targets

    const int T = 256;
    int nv = (n + 3) / 4;
    int gv = (nv + T - 1) / T;

    k_init<<<(NODE_CAP + T - 1) / T, T>>>();
    k_max <<<gv, T>>>(e, tgt, n);
    k_sum <<<gv, T>>>(e, tgt, n);
    k_norm<<<gv, T>>>(e, tgt, out, n);
}

// round 4
// speedup vs baseline: 1.8574x; 1.8574x over previous
#include <cuda_runtime.h>
#include <cstdint>

#define NODE_CAP 102400   // >= num_nodes (100000)

// Scratch (allocation-free per harness rules). Holds sum(exp) then 1/(sum+eps).
__device__ float g_sumexp[NODE_CAP];

// ---------------- init: zero sums ----------------
__global__ void k_init() {
    int i = blockIdx.x * blockDim.x + threadIdx.x;
    if (i < NODE_CAP) g_sumexp[i] = 0.0f;
}

// ---------------- pass 1: atomic sum of exp(e) ----------------
// 8 edges per thread (two float4/int4 loads) for load MLP.
__global__ void k_sum(const float* __restrict__ e,
                      const int* __restrict__ tgt, int n) {
    int v = blockIdx.x * blockDim.x + threadIdx.x;
    int base = v * 8;
    if (base + 7 < n) {
        float4 e0 = reinterpret_cast<const float4*>(e)[2 * v];
        float4 e1 = reinterpret_cast<const float4*>(e)[2 * v + 1];
        int4   t0 = reinterpret_cast<const int4*>(tgt)[2 * v];
        int4   t1 = reinterpret_cast<const int4*>(tgt)[2 * v + 1];
        atomicAdd(&g_sumexp[t0.x], __expf(e0.x));
        atomicAdd(&g_sumexp[t0.y], __expf(e0.y));
        atomicAdd(&g_sumexp[t0.z], __expf(e0.z));
        atomicAdd(&g_sumexp[t0.w], __expf(e0.w));
        atomicAdd(&g_sumexp[t1.x], __expf(e1.x));
        atomicAdd(&g_sumexp[t1.y], __expf(e1.y));
        atomicAdd(&g_sumexp[t1.z], __expf(e1.z));
        atomicAdd(&g_sumexp[t1.w], __expf(e1.w));
    } else {
        for (int i = base; i < n; i++)
            atomicAdd(&g_sumexp[tgt[i]], __expf(e[i]));
    }
}

// ---------------- pass 2: reciprocal in place ----------------
__global__ void k_rcp() {
    int i = blockIdx.x * blockDim.x + threadIdx.x;
    if (i < NODE_CAP) g_sumexp[i] = 1.0f / (g_sumexp[i] + 1e-16f);
}

// ---------------- pass 3: alpha = exp(e) * rcp[t] ----------------
__global__ void k_norm(const float* __restrict__ e,
                       const int* __restrict__ tgt,
                       float* __restrict__ out, int n) {
    int v = blockIdx.x * blockDim.x + threadIdx.x;
    int base = v * 8;
    if (base + 7 < n) {
        float4 e0 = reinterpret_cast<const float4*>(e)[2 * v];
        float4 e1 = reinterpret_cast<const float4*>(e)[2 * v + 1];
        int4   t0 = reinterpret_cast<const int4*>(tgt)[2 * v];
        int4   t1 = reinterpret_cast<const int4*>(tgt)[2 * v + 1];
        // Issue all gathers before the math so they overlap.
        float r0 = __ldg(&g_sumexp[t0.x]);
        float r1 = __ldg(&g_sumexp[t0.y]);
        float r2 = __ldg(&g_sumexp[t0.z]);
        float r3 = __ldg(&g_sumexp[t0.w]);
        float r4 = __ldg(&g_sumexp[t1.x]);
        float r5 = __ldg(&g_sumexp[t1.y]);
        float r6 = __ldg(&g_sumexp[t1.z]);
        float r7 = __ldg(&g_sumexp[t1.w]);
        float4 o0, o1;
        o0.x = __expf(e0.x) * r0;
        o0.y = __expf(e0.y) * r1;
        o0.z = __expf(e0.z) * r2;
        o0.w = __expf(e0.w) * r3;
        o1.x = __expf(e1.x) * r4;
        o1.y = __expf(e1.y) * r5;
        o1.z = __expf(e1.z) * r6;
        o1.w = __expf(e1.w) * r7;
        reinterpret_cast<float4*>(out)[2 * v]     = o0;
        reinterpret_cast<float4*>(out)[2 * v + 1] = o1;
    } else {
        for (int i = base; i < n; i++)
            out[i] = __expf(e[i]) * g_sumexp[tgt[i]];
    }
}

extern "C" void kernel_launch(void* const* d_in, const int* in_sizes, int n_in,
                              void* d_out, int out_size) {
    const float* e   = (const float*)d_in[0];
    const int*   ei  = (const int*)d_in[1];   // int32 [2, n]
    float*       out = (float*)d_out;
    int n = in_sizes[0];
    const int* tgt = ei + n;  // row 1 = targets

    const int T = 256;
    int nv = (n + 7) / 8;
    int gv = (nv + T - 1) / T;
    int gn = (NODE_CAP + T - 1) / T;

    k_init<<<gn, T>>>();
    k_sum <<<gv, T>>>(e, tgt, n);
    k_rcp <<<gn, T>>>();
    k_norm<<<gv, T>>>(e, tgt, out, n);
}

// round 5
// speedup vs baseline: 2.0093x; 1.0817x over previous
#include <cuda_runtime.h>
#include <cstdint>

#define NODE_CAP 102400        // >= num_nodes (100000)
#define TABLE    57344         // nodes cached in smem (57344*4 = 229376 B <= 232448)

// Scratch (allocation-free). Holds sum(exp) then 1/(sum+eps).
__device__ float g_sumexp[NODE_CAP];

// ---------------- init: zero sums ----------------
__global__ void k_init() {
    int i = blockIdx.x * blockDim.x + threadIdx.x;
    if (i < NODE_CAP) g_sumexp[i] = 0.0f;
}

// ---------------- pass 1: atomic sum of exp(e) ----------------
__global__ void k_sum(const float* __restrict__ e,
                      const int* __restrict__ tgt, int n) {
    int v = blockIdx.x * blockDim.x + threadIdx.x;
    int base = v * 8;
    if (base + 7 < n) {
        float4 e0 = reinterpret_cast<const float4*>(e)[2 * v];
        float4 e1 = reinterpret_cast<const float4*>(e)[2 * v + 1];
        int4   t0 = reinterpret_cast<const int4*>(tgt)[2 * v];
        int4   t1 = reinterpret_cast<const int4*>(tgt)[2 * v + 1];
        atomicAdd(&g_sumexp[t0.x], __expf(e0.x));
        atomicAdd(&g_sumexp[t0.y], __expf(e0.y));
        atomicAdd(&g_sumexp[t0.z], __expf(e0.z));
        atomicAdd(&g_sumexp[t0.w], __expf(e0.w));
        atomicAdd(&g_sumexp[t1.x], __expf(e1.x));
        atomicAdd(&g_sumexp[t1.y], __expf(e1.y));
        atomicAdd(&g_sumexp[t1.z], __expf(e1.z));
        atomicAdd(&g_sumexp[t1.w], __expf(e1.w));
    } else {
        for (int i = base; i < n; i++)
            atomicAdd(&g_sumexp[tgt[i]], __expf(e[i]));
    }
}

// ---------------- pass 2: reciprocal in place ----------------
__global__ void k_rcp() {
    int i = blockIdx.x * blockDim.x + threadIdx.x;
    if (i < NODE_CAP) g_sumexp[i] = 1.0f / (g_sumexp[i] + 1e-16f);
}

// ---------------- pass 3: hybrid smem-table normalize ----------------
// Grid-stride persistent: 148 CTAs x 1024 threads, 224 KB smem table each.
__global__ void __launch_bounds__(1024, 1)
k_norm(const float* __restrict__ e,
       const int* __restrict__ tgt,
       float* __restrict__ out, int n) {
    extern __shared__ float s_rcp[];   // TABLE floats

    // Cooperative table load (vectorized): TABLE/4 float4s.
    const float4* g4 = reinterpret_cast<const float4*>(g_sumexp);
    float4* s4 = reinterpret_cast<float4*>(s_rcp);
    for (int i = threadIdx.x; i < TABLE / 4; i += blockDim.x)
        s4[i] = g4[i];
    __syncthreads();

    int nv = n >> 2;                   // whole float4 groups
    int stride = gridDim.x * blockDim.x;
    int tid = blockIdx.x * blockDim.x + threadIdx.x;

    for (int v = tid; v < nv; v += stride) {
        float4 ev = reinterpret_cast<const float4*>(e)[v];
        int4   t  = reinterpret_cast<const int4*>(tgt)[v];
        float r0 = (t.x < TABLE) ? s_rcp[t.x] : __ldg(&g_sumexp[t.x]);
        float r1 = (t.y < TABLE) ? s_rcp[t.y] : __ldg(&g_sumexp[t.y]);
        float r2 = (t.z < TABLE) ? s_rcp[t.z] : __ldg(&g_sumexp[t.z]);
        float r3 = (t.w < TABLE) ? s_rcp[t.w] : __ldg(&g_sumexp[t.w]);
        float4 o;
        o.x = __expf(ev.x) * r0;
        o.y = __expf(ev.y) * r1;
        o.z = __expf(ev.z) * r2;
        o.w = __expf(ev.w) * r3;
        reinterpret_cast<float4*>(out)[v] = o;
    }

    // Tail (n % 4), handled by first threads of block 0.
    if (blockIdx.x == 0) {
        for (int i = (nv << 2) + threadIdx.x; i < n; i += blockDim.x) {
            int t = tgt[i];
            float r = (t < TABLE) ? s_rcp[t] : __ldg(&g_sumexp[t]);
            out[i] = __expf(e[i]) * r;
        }
    }
}

extern "C" void kernel_launch(void* const* d_in, const int* in_sizes, int n_in,
                              void* d_out, int out_size) {
    const float* e   = (const float*)d_in[0];
    const int*   ei  = (const int*)d_in[1];   // int32 [2, n]
    float*       out = (float*)d_out;
    int n = in_sizes[0];
    const int* tgt = ei + n;  // row 1 = targets

    const int T = 256;
    int nv = (n + 7) / 8;
    int gv = (nv + T - 1) / T;
    int gn = (NODE_CAP + T - 1) / T;

    static bool attr_done = false;
    if (!attr_done) {
        cudaFuncSetAttribute(k_norm, cudaFuncAttributeMaxDynamicSharedMemorySize,
                             TABLE * (int)sizeof(float));
        attr_done = true;
    }

    k_init<<<gn, T>>>();
    k_sum <<<gv, T>>>(e, tgt, n);
    k_rcp <<<gn, T>>>();
    k_norm<<<148, 1024, TABLE * sizeof(float)>>>(e, tgt, out, n);
}

// round 6
// speedup vs baseline: 2.0218x; 1.0062x over previous
#include <cuda_runtime.h>
#include <cstdint>

#define NODE_CAP 102400   // >= num_nodes (100000)

// Scratch (allocation-free). Holds sum(exp) then 1/(sum+eps).
__device__ float g_sumexp[NODE_CAP];

// ---------------- init: zero sums ----------------
__global__ void k_init() {
    int i = blockIdx.x * blockDim.x + threadIdx.x;
    if (i < NODE_CAP) g_sumexp[i] = 0.0f;
}

// ---------------- pass 1: atomic sum of exp(e), 8 edges/thread ----------------
__global__ void k_sum(const float* __restrict__ e,
                      const int* __restrict__ tgt, int n) {
    int v = blockIdx.x * blockDim.x + threadIdx.x;
    int base = v * 8;
    if (base + 7 < n) {
        float4 e0 = reinterpret_cast<const float4*>(e)[2 * v];
        float4 e1 = reinterpret_cast<const float4*>(e)[2 * v + 1];
        int4   t0 = reinterpret_cast<const int4*>(tgt)[2 * v];
        int4   t1 = reinterpret_cast<const int4*>(tgt)[2 * v + 1];
        atomicAdd(&g_sumexp[t0.x], __expf(e0.x));
        atomicAdd(&g_sumexp[t0.y], __expf(e0.y));
        atomicAdd(&g_sumexp[t0.z], __expf(e0.z));
        atomicAdd(&g_sumexp[t0.w], __expf(e0.w));
        atomicAdd(&g_sumexp[t1.x], __expf(e1.x));
        atomicAdd(&g_sumexp[t1.y], __expf(e1.y));
        atomicAdd(&g_sumexp[t1.z], __expf(e1.z));
        atomicAdd(&g_sumexp[t1.w], __expf(e1.w));
    } else {
        for (int i = base; i < n; i++)
            atomicAdd(&g_sumexp[tgt[i]], __expf(e[i]));
    }
}

// ---------------- pass 2: reciprocal in place ----------------
__global__ void k_rcp() {
    int i = blockIdx.x * blockDim.x + threadIdx.x;
    if (i < NODE_CAP) g_sumexp[i] = 1.0f / (g_sumexp[i] + 1e-16f);
}

// ---------------- pass 3: alpha = exp(e) * rcp[t], 8 edges/thread ----------------
__global__ void k_norm(const float* __restrict__ e,
                       const int* __restrict__ tgt,
                       float* __restrict__ out, int n) {
    int v = blockIdx.x * blockDim.x + threadIdx.x;
    int base = v * 8;
    if (base + 7 < n) {
        float4 e0 = reinterpret_cast<const float4*>(e)[2 * v];
        float4 e1 = reinterpret_cast<const float4*>(e)[2 * v + 1];
        int4   t0 = reinterpret_cast<const int4*>(tgt)[2 * v];
        int4   t1 = reinterpret_cast<const int4*>(tgt)[2 * v + 1];
        // Batch all gathers first so they overlap in the L1tex queue.
        float r0 = __ldg(&g_sumexp[t0.x]);
        float r1 = __ldg(&g_sumexp[t0.y]);
        float r2 = __ldg(&g_sumexp[t0.z]);
        float r3 = __ldg(&g_sumexp[t0.w]);
        float r4 = __ldg(&g_sumexp[t1.x]);
        float r5 = __ldg(&g_sumexp[t1.y]);
        float r6 = __ldg(&g_sumexp[t1.z]);
        float r7 = __ldg(&g_sumexp[t1.w]);
        float4 o0, o1;
        o0.x = __expf(e0.x) * r0;
        o0.y = __expf(e0.y) * r1;
        o0.z = __expf(e0.z) * r2;
        o0.w = __expf(e0.w) * r3;
        o1.x = __expf(e1.x) * r4;
        o1.y = __expf(e1.y) * r5;
        o1.z = __expf(e1.z) * r6;
        o1.w = __expf(e1.w) * r7;
        reinterpret_cast<float4*>(out)[2 * v]     = o0;
        reinterpret_cast<float4*>(out)[2 * v + 1] = o1;
    } else {
        for (int i = base; i < n; i++)
            out[i] = __expf(e[i]) * g_sumexp[tgt[i]];
    }
}

extern "C" void kernel_launch(void* const* d_in, const int* in_sizes, int n_in,
                              void* d_out, int out_size) {
    const float* e   = (const float*)d_in[0];
    const int*   ei  = (const int*)d_in[1];   // int32 [2, n]
    float*       out = (float*)d_out;
    int n = in_sizes[0];
    const int* tgt = ei + n;  // row 1 = targets

    const int T = 256;
    int nv = (n + 7) / 8;
    int gv = (nv + T - 1) / T;
    int gn = (NODE_CAP + T - 1) / T;

    k_init<<<gn, T>>>();
    k_sum <<<gv, T>>>(e, tgt, n);
    k_rcp <<<gn, T>>>();
    k_norm<<<gv, T>>>(e, tgt, out, n);
}